// round 10
// baseline (speedup 1.0000x reference)
#include <cuda_runtime.h>

// Problem constants (fixed by setup_inputs): x[B, T, C], pool over T.
#define PB 32
#define PT 8192
#define PC 256
#define NSPLIT 16                 // T-chunks per batch -> grid 512 (best-measured residency)
#define TCHUNK (PT / NSPLIT)      // 512 timesteps per block
#define TLANES 4                  // time-lanes inside a block
#define ITERS (TCHUNK / TLANES)   // 128 float4 loads per thread
#define C4 (PC / 4)               // 64 float4 per row
#define NMOM 5                    // y, y^2, y^3, y^4, x^p

// Scratch: [B][NSPLIT][NMOM][C] floats = 32*16*5*256*4 = 2.6 MB (L2-resident
// at reduce time: written immediately before being read by the last block).
__device__ float g_scratch[PB * NSPLIT * NMOM * PC];
// Per-batch arrival counters (zero-initialized at module load; the reducer
// block resets its counter to 0, keeping the invariant across graph replays).
__device__ int g_count[PB];

// ---------------------------------------------------------------------------
// Fused kernel: per (batch, T-chunk) partial shifted moments + last-block
// reduction (threadFenceReduction pattern). Epilogue algebra is all-fp32
// (cancellation factors are O(1) thanks to the y = x - 0.5 shift).
// launch_bounds(256,8) forces the 32-reg allocation that the standalone
// streaming kernel compiles to — R7 showed the same loop at 40 regs loses
// ~0.7 TB/s of streaming bandwidth.
// ---------------------------------------------------------------------------
__global__ __launch_bounds__(256, 8)
void hom_fused(const float* __restrict__ x, const float* __restrict__ p_ptr,
               float* __restrict__ out)
{
    const int b     = blockIdx.y;
    const int chunk = blockIdx.x;
    const int tid   = threadIdx.x;
    const int c4    = tid & (C4 - 1);   // 0..63  channel group
    const int tl    = tid >> 6;         // 0..3   time lane

    const float p = p_ptr[0];
    const bool p_is_one = (p == 1.0f);

    const float4* __restrict__ x4 = reinterpret_cast<const float4*>(x);
    const int t0   = chunk * TCHUNK + tl;
    int idx        = (b * PT + t0) * C4 + c4;   // max ~16.8M, fits int
    const int step = TLANES * C4;

    float4 s1 = make_float4(0.f, 0.f, 0.f, 0.f);
    float4 s2 = s1, s3 = s1, s4 = s1, sp = s1;

    if (p_is_one) {
        #pragma unroll 4
        for (int i = 0; i < ITERS; ++i, idx += step) {
            float4 v = x4[idx];
            {
                float y = v.x - 0.5f, y2 = y * y;
                s1.x += y; s2.x += y2; s3.x += y2 * y; s4.x += y2 * y2;
            }
            {
                float y = v.y - 0.5f, y2 = y * y;
                s1.y += y; s2.y += y2; s3.y += y2 * y; s4.y += y2 * y2;
            }
            {
                float y = v.z - 0.5f, y2 = y * y;
                s1.z += y; s2.z += y2; s3.z += y2 * y; s4.z += y2 * y2;
            }
            {
                float y = v.w - 0.5f, y2 = y * y;
                s1.w += y; s2.w += y2; s3.w += y2 * y; s4.w += y2 * y2;
            }
        }
        // sp stays zero; the reducer derives grp = E[y] + 0.5 when p==1.
    } else {
        #pragma unroll 2
        for (int i = 0; i < ITERS; ++i, idx += step) {
            float4 v = x4[idx];
            {
                float y = v.x - 0.5f, y2 = y * y;
                s1.x += y; s2.x += y2; s3.x += y2 * y; s4.x += y2 * y2;
                sp.x += powf(v.x, p);
            }
            {
                float y = v.y - 0.5f, y2 = y * y;
                s1.y += y; s2.y += y2; s3.y += y2 * y; s4.y += y2 * y2;
                sp.y += powf(v.y, p);
            }
            {
                float y = v.z - 0.5f, y2 = y * y;
                s1.z += y; s2.z += y2; s3.z += y2 * y; s4.z += y2 * y2;
                sp.z += powf(v.z, p);
            }
            {
                float y = v.w - 0.5f, y2 = y * y;
                s1.w += y; s2.w += y2; s3.w += y2 * y; s4.w += y2 * y2;
                sp.w += powf(v.w, p);
            }
        }
    }

    // Reduce the 4 time-lanes through shared memory.
    __shared__ float4 sm[TLANES][NMOM][C4];   // 20 KB
    sm[tl][0][c4] = s1;
    sm[tl][1][c4] = s2;
    sm[tl][2][c4] = s3;
    sm[tl][3][c4] = s4;
    sm[tl][4][c4] = sp;
    __syncthreads();

    float4* __restrict__ sc4 = reinterpret_cast<float4*>(g_scratch);
    const int pbase = ((b * NSPLIT + chunk) * NMOM) * C4;
    for (int w = tid; w < NMOM * C4; w += 256) {
        const int m = w / C4;
        const int c = w - m * C4;
        float4 a = sm[0][m][c];
        float4 bq = sm[1][m][c];
        float4 cq = sm[2][m][c];
        float4 dq = sm[3][m][c];
        float4 r;
        r.x = (a.x + bq.x) + (cq.x + dq.x);
        r.y = (a.y + bq.y) + (cq.y + dq.y);
        r.z = (a.z + bq.z) + (cq.z + dq.z);
        r.w = (a.w + bq.w) + (cq.w + dq.w);
        sc4[pbase + w] = r;
    }

    // ---- last-block-per-batch reduction (threadFenceReduction pattern) ----
    __threadfence();  // make this block's scratch stores visible device-wide

    __shared__ int is_last;
    if (tid == 0)
        is_last = (atomicAdd(&g_count[b], 1) == NSPLIT - 1);
    __syncthreads();
    if (!is_last) return;

    if (tid == 0) g_count[b] = 0;   // reset for the next graph replay

    // Reducer: 256 threads = 64 channel-groups x 4 split lanes.
    // Each lane sums 4 splits x 5 moments = 20 independent L2-hit LDG.128.
    {
        const int rc4 = tid & (C4 - 1);   // 0..63 float4 group
        const int rsl = tid >> 6;         // 0..3  split lane

        float4 acc[NMOM];
        #pragma unroll
        for (int m = 0; m < NMOM; ++m) acc[m] = make_float4(0.f, 0.f, 0.f, 0.f);

        #pragma unroll
        for (int i = 0; i < NSPLIT / TLANES; ++i) {
            const int s  = rsl * (NSPLIT / TLANES) + i;
            const int bi = ((b * NSPLIT + s) * NMOM) * C4 + rc4;
            #pragma unroll
            for (int m = 0; m < NMOM; ++m) {
                float4 v = sc4[bi + m * C4];
                acc[m].x += v.x; acc[m].y += v.y;
                acc[m].z += v.z; acc[m].w += v.w;
            }
        }

        __syncthreads();  // sm[] reuse: everyone is past the store loop above
        #pragma unroll
        for (int m = 0; m < NMOM; ++m)
            sm[rsl][m][rc4] = acc[m];
        __syncthreads();

        // Collapse the 4 split lanes (lane 0 holds the total).
        if (rsl == 0) {
            #pragma unroll
            for (int m = 0; m < NMOM; ++m) {
                float4 a  = sm[0][m][rc4];
                float4 bq = sm[1][m][rc4];
                float4 cq = sm[2][m][rc4];
                float4 dq = sm[3][m][rc4];
                a.x = (a.x + bq.x) + (cq.x + dq.x);
                a.y = (a.y + bq.y) + (cq.y + dq.y);
                a.z = (a.z + bq.z) + (cq.z + dq.z);
                a.w = (a.w + bq.w) + (cq.w + dq.w);
                sm[0][m][rc4] = a;
            }
        }
        __syncthreads();

        // Final algebra: one channel per thread (256 channels), all fp32.
        const int g    = tid >> 2;   // float4 group
        const int comp = tid & 3;    // component
        float t[NMOM];
        #pragma unroll
        for (int m = 0; m < NMOM; ++m) {
            float4 v = sm[0][m][g];
            t[m] = (comp == 0) ? v.x : (comp == 1) ? v.y
                 : (comp == 2) ? v.z : v.w;
        }

        const float invT = 1.0f / (float)PT;
        const float d  = t[0] * invT;   // E[y],  y = x - 0.5
        const float e2 = t[1] * invT;   // E[y^2]
        const float e3 = t[2] * invT;   // E[y^3]
        const float e4 = t[3] * invT;   // E[y^4]

        const float d2  = d * d;
        const float var = e2 - d2;
        const float m3  = e3 - 3.0f * d * e2 + 2.0f * d * d2;
        const float m4  = e4 - 4.0f * d * e3 + 6.0f * d2 * e2 - 3.0f * d2 * d2;

        const float grp = p_is_one ? (d + 0.5f) : (t[4] * invT);

        const float stdv = sqrtf(var + 1e-6f);
        const float st3  = stdv * stdv * stdv;

        float* o = out + b * (4 * PC);
        o[tid]          = grp;
        o[PC + tid]     = var;
        o[2 * PC + tid] = m3 / st3;
        o[3 * PC + tid] = m4 / (st3 * stdv);
    }
}

extern "C" void kernel_launch(void* const* d_in, const int* in_sizes, int n_in,
                              void* d_out, int out_size)
{
    const float* x = (const float*)d_in[0];
    const float* p = (const float*)d_in[1];
    float* out     = (float*)d_out;

    dim3 grid(NSPLIT, PB);
    hom_fused<<<grid, 256>>>(x, p, out);
}

// round 12
// speedup vs baseline: 1.2085x; 1.2085x over previous
#include <cuda_runtime.h>

// Problem constants (fixed by setup_inputs): x[B, T, C], pool over T.
#define PB 32
#define PT 8192
#define PC 256
#define NSPLIT 16                 // T-chunks per batch
#define TCHUNK (PT / NSPLIT)      // 512 timesteps per block
#define TLANES 4                  // time-lanes inside a block
#define ITERS (TCHUNK / TLANES)   // 128 float4 loads per thread
#define C4 (PC / 4)               // 64 float4 per row
#define NMOM 5                    // y, y^2, y^3, y^4, x^p

// Scratch: [B][NSPLIT][NMOM][C] floats = 32*16*5*256*4 = 2.6 MB
__device__ float g_scratch[PB * NSPLIT * NMOM * PC];

// ---------------------------------------------------------------------------
// Pass 1: per (batch, T-chunk) partial shifted moments. EXACT copy of the
// proven 6.45 TB/s streaming kernel (R4), plus a PDL trigger after the main
// loop so pass2's launch ramp overlaps pass1's store-drain tail.
// Shift y = x - 0.5 keeps all cancellation factors O(1) for uniform-ish data
// while remaining algebraically exact for any input.
// ---------------------------------------------------------------------------
__global__ __launch_bounds__(256)
void hom_pass1(const float* __restrict__ x, const float* __restrict__ p_ptr)
{
    const int b     = blockIdx.y;
    const int chunk = blockIdx.x;
    const int tid   = threadIdx.x;
    const int c4    = tid & (C4 - 1);   // 0..63  channel group
    const int tl    = tid >> 6;         // 0..3   time lane

    const float p = p_ptr[0];
    const bool p_is_one = (p == 1.0f);

    const float4* __restrict__ x4 = reinterpret_cast<const float4*>(x);
    const int t0   = chunk * TCHUNK + tl;
    int idx        = (b * PT + t0) * C4 + c4;   // max ~16.8M, fits int
    const int step = TLANES * C4;

    float4 s1 = make_float4(0.f, 0.f, 0.f, 0.f);
    float4 s2 = s1, s3 = s1, s4 = s1, sp = s1;

    if (p_is_one) {
        #pragma unroll 4
        for (int i = 0; i < ITERS; ++i, idx += step) {
            float4 v = x4[idx];
            {
                float y = v.x - 0.5f, y2 = y * y;
                s1.x += y; s2.x += y2; s3.x += y2 * y; s4.x += y2 * y2;
            }
            {
                float y = v.y - 0.5f, y2 = y * y;
                s1.y += y; s2.y += y2; s3.y += y2 * y; s4.y += y2 * y2;
            }
            {
                float y = v.z - 0.5f, y2 = y * y;
                s1.z += y; s2.z += y2; s3.z += y2 * y; s4.z += y2 * y2;
            }
            {
                float y = v.w - 0.5f, y2 = y * y;
                s1.w += y; s2.w += y2; s3.w += y2 * y; s4.w += y2 * y2;
            }
        }
        // sp stays zero; pass 2 derives grp = E[y] + 0.5 when p==1.
    } else {
        #pragma unroll 2
        for (int i = 0; i < ITERS; ++i, idx += step) {
            float4 v = x4[idx];
            {
                float y = v.x - 0.5f, y2 = y * y;
                s1.x += y; s2.x += y2; s3.x += y2 * y; s4.x += y2 * y2;
                sp.x += powf(v.x, p);
            }
            {
                float y = v.y - 0.5f, y2 = y * y;
                s1.y += y; s2.y += y2; s3.y += y2 * y; s4.y += y2 * y2;
                sp.y += powf(v.y, p);
            }
            {
                float y = v.z - 0.5f, y2 = y * y;
                s1.z += y; s2.z += y2; s3.z += y2 * y; s4.z += y2 * y2;
                sp.z += powf(v.z, p);
            }
            {
                float y = v.w - 0.5f, y2 = y * y;
                s1.w += y; s2.w += y2; s3.w += y2 * y; s4.w += y2 * y2;
                sp.w += powf(v.w, p);
            }
        }
    }

    // Streaming work done: let the dependent pass2 start its launch ramp now.
    // (Its grid-dependency sync still waits for this kernel's full completion
    // and memory visibility before it reads g_scratch.)
    cudaTriggerProgrammaticLaunchCompletion();

    // Reduce the 4 time-lanes through shared memory.
    __shared__ float4 sm[TLANES][NMOM][C4];   // 20 KB
    sm[tl][0][c4] = s1;
    sm[tl][1][c4] = s2;
    sm[tl][2][c4] = s3;
    sm[tl][3][c4] = s4;
    sm[tl][4][c4] = sp;
    __syncthreads();

    float4* __restrict__ sc4 = reinterpret_cast<float4*>(g_scratch);
    const int pbase = ((b * NSPLIT + chunk) * NMOM) * C4;
    for (int w = tid; w < NMOM * C4; w += 256) {
        const int m = w / C4;
        const int c = w - m * C4;
        float4 a = sm[0][m][c];
        float4 bq = sm[1][m][c];
        float4 cq = sm[2][m][c];
        float4 dq = sm[3][m][c];
        float4 r;
        r.x = (a.x + bq.x) + (cq.x + dq.x);
        r.y = (a.y + bq.y) + (cq.y + dq.y);
        r.z = (a.z + bq.z) + (cq.z + dq.z);
        r.w = (a.w + bq.w) + (cq.w + dq.w);
        sc4[pbase + w] = r;
    }
}

// ---------------------------------------------------------------------------
// Pass 2: grid (PB, 4). Block = 256 threads = 16 float4-channel-groups x 16
// split lanes; each lane reads exactly ONE split (5 LDG.128). Launched with
// programmatic stream serialization: the prologue overlaps pass1's tail, and
// cudaGridDependencySynchronize() gates the scratch reads.
// ---------------------------------------------------------------------------
#define P2_CG    4                  // channel-quarter groups (gridDim.y)
#define P2_C4PB  (C4 / P2_CG)       // 16 float4 groups (64 channels) per block
#define P2_SL    NSPLIT             // 16 split lanes, one split each

__global__ __launch_bounds__(256)
void hom_pass2(const float* __restrict__ p_ptr, float* __restrict__ out)
{
    const int b   = blockIdx.x;
    const int cg  = blockIdx.y;
    const int tid = threadIdx.x;
    const int cl  = tid & (P2_C4PB - 1);  // 0..15 float4 group within block
    const int sl  = tid >> 4;             // 0..15 split lane
    const int c4g = cg * P2_C4PB + cl;    // global float4 group (0..63)

    const float4* __restrict__ sc4 = reinterpret_cast<const float4*>(g_scratch);
    const int base = ((b * NSPLIT + sl) * NMOM) * C4 + c4g;

    // Wait for pass1 (and its scratch stores) to be visible.
    cudaGridDependencySynchronize();

    // One split per lane: 5 independent LDG.128 (L2-dirty hits).
    float4 acc[NMOM];
    #pragma unroll
    for (int m = 0; m < NMOM; ++m)
        acc[m] = sc4[base + m * C4];

    __shared__ float4 sm[P2_SL][NMOM][P2_C4PB];   // 25.6 KB
    #pragma unroll
    for (int m = 0; m < NMOM; ++m)
        sm[sl][m][cl] = acc[m];
    __syncthreads();

    // Tree-reduce the 16 split lanes.
    for (int off = P2_SL / 2; off >= 1; off >>= 1) {
        if (sl < off) {
            #pragma unroll
            for (int m = 0; m < NMOM; ++m) {
                float4 a = sm[sl][m][cl];
                float4 bq = sm[sl + off][m][cl];
                a.x += bq.x; a.y += bq.y; a.z += bq.z; a.w += bq.w;
                sm[sl][m][cl] = a;
            }
        }
        __syncthreads();
    }

    // Final algebra: 64 channels per block -> threads 0..63, one channel each.
    if (tid < 4 * P2_C4PB) {
        const int g    = tid >> 2;         // float4 group 0..15
        const int comp = tid & 3;          // component within float4
        const int c    = cg * P2_C4PB * 4 + g * 4 + comp;  // global channel

        double t[NMOM];
        #pragma unroll
        for (int m = 0; m < NMOM; ++m) {
            float4 v = sm[0][m][g];
            t[m] = (double)((comp == 0) ? v.x : (comp == 1) ? v.y
                          : (comp == 2) ? v.z : v.w);
        }

        const double invT = 1.0 / (double)PT;
        const double d  = t[0] * invT;   // E[y],  y = x - 0.5
        const double e2 = t[1] * invT;   // E[y^2]
        const double e3 = t[2] * invT;   // E[y^3]
        const double e4 = t[3] * invT;   // E[y^4]

        const double d2  = d * d;
        const double var = e2 - d2;
        const double m3  = e3 - 3.0 * d * e2 + 2.0 * d * d2;
        const double m4  = e4 - 4.0 * d * e3 + 6.0 * d2 * e2 - 3.0 * d2 * d2;

        const float p = p_ptr[0];
        const double grp = (p == 1.0f) ? (d + 0.5) : (t[4] * invT);

        const double stdv = sqrt(var + 1e-6);
        const double st3  = stdv * stdv * stdv;

        float* o = out + b * (4 * PC);
        o[c]          = (float)grp;
        o[PC + c]     = (float)var;
        o[2 * PC + c] = (float)(m3 / st3);
        o[3 * PC + c] = (float)(m4 / (st3 * stdv));
    }
}

extern "C" void kernel_launch(void* const* d_in, const int* in_sizes, int n_in,
                              void* d_out, int out_size)
{
    const float* x = (const float*)d_in[0];
    const float* p = (const float*)d_in[1];
    float* out     = (float*)d_out;

    dim3 grid1(NSPLIT, PB);
    hom_pass1<<<grid1, 256>>>(x, p);

    // Pass 2 with programmatic dependent launch: ramp overlaps pass1's tail.
    cudaLaunchConfig_t cfg = {};
    cfg.gridDim  = dim3(PB, P2_CG);
    cfg.blockDim = dim3(256, 1, 1);
    cfg.dynamicSmemBytes = 0;
    cfg.stream = 0;   // same (capture) stream as pass1

    cudaLaunchAttribute attrs[1];
    attrs[0].id = cudaLaunchAttributeProgrammaticStreamSerialization;
    attrs[0].val.programmaticStreamSerializationAllowed = 1;
    cfg.attrs = attrs;
    cfg.numAttrs = 1;

    cudaLaunchKernelEx(&cfg, hom_pass2, p, out);
}

// round 15
// speedup vs baseline: 1.2933x; 1.0701x over previous
#include <cuda_runtime.h>

// Problem constants (fixed by setup_inputs): x[B, T, C], pool over T.
#define PB 32
#define PT 8192
#define PC 256
#define NSPLIT 16                 // T-chunks per batch -> grid 512 (one wave)
#define TCHUNK (PT / NSPLIT)      // 512 timesteps per block
#define TLANES 4                  // time-lanes inside a block
#define ITERS (TCHUNK / TLANES)   // 128 float4 loads per thread
#define C4 (PC / 4)               // 64 float4 per row
#define NMOM 5                    // y, y^2, y^3, y^4, x^p

// Global accumulators: [B][NMOM][C] floats = 160 KB. Zero-initialized at load;
// the per-batch reducer block zeroes them again after reading, so every graph
// replay starts from zeros (deterministic up to fp32 atomic ordering noise).
__device__ float g_sums[PB * NMOM * PC];
// Per-batch arrival counters, same self-resetting discipline.
__device__ int g_count[PB];

// ---------------------------------------------------------------------------
// Tail: __noinline__ so the streaming loop's compiled schedule (its load
// front-batching is worth ~0.7 TB/s) is isolated from this code.
// Reduces 4 time-lanes in smem, atomically folds 5*256 partial sums per block
// into g_sums, and lets the last-arriving block of each batch finish the
// (all-fp32, cancellation-safe) moment algebra.
// ---------------------------------------------------------------------------
__device__ __noinline__ void hom_tail(
    float4 s1, float4 s2, float4 s3, float4 s4, float4 sp,
    int b, int tid, int c4, int tl, bool p_is_one, float p_val,
    float* __restrict__ out)
{
    __shared__ float4 sm[TLANES][NMOM][C4];   // 20 KB
    sm[tl][0][c4] = s1;
    sm[tl][1][c4] = s2;
    sm[tl][2][c4] = s3;
    sm[tl][3][c4] = s4;
    sm[tl][4][c4] = sp;
    __syncthreads();

    // Each thread owns one channel c = tid: collapse 4 lanes, 5 atomics.
    {
        const int g    = tid >> 2;   // float4 group
        const int comp = tid & 3;    // component
        #pragma unroll
        for (int m = 0; m < NMOM; ++m) {
            float v = 0.f;
            #pragma unroll
            for (int k = 0; k < TLANES; ++k) {
                float4 q = sm[k][m][g];
                v += (comp == 0) ? q.x : (comp == 1) ? q.y
                   : (comp == 2) ? q.z : q.w;
            }
            atomicAdd(&g_sums[(b * NMOM + m) * PC + tid], v);
        }
    }

    // ---- last-block-per-batch epilogue ----
    __threadfence();   // make this block's REDs visible before counter bump

    __shared__ int is_last;
    if (tid == 0)
        is_last = (atomicAdd(&g_count[b], 1) == NSPLIT - 1);
    __syncthreads();
    if (!is_last) return;

    if (tid == 0) g_count[b] = 0;   // reset for the next graph replay

    // Read the 5 accumulated moments for channel tid (L2, bypass L1), then
    // zero them for the next replay.
    float t[NMOM];
    #pragma unroll
    for (int m = 0; m < NMOM; ++m) {
        float* a = &g_sums[(b * NMOM + m) * PC + tid];
        t[m] = __ldcg(a);
        __stcg(a, 0.f);
    }

    const float invT = 1.0f / (float)PT;
    const float d  = t[0] * invT;   // E[y],  y = x - 0.5
    const float e2 = t[1] * invT;   // E[y^2]
    const float e3 = t[2] * invT;   // E[y^3]
    const float e4 = t[3] * invT;   // E[y^4]

    const float d2  = d * d;
    const float var = e2 - d2;
    const float m3  = e3 - 3.0f * d * e2 + 2.0f * d * d2;
    const float m4  = e4 - 4.0f * d * e3 + 6.0f * d2 * e2 - 3.0f * d2 * d2;

    const float grp = p_is_one ? (d + 0.5f) : (t[4] * invT);

    const float stdv = sqrtf(var + 1e-6f);
    const float st3  = stdv * stdv * stdv;

    float* o = out + b * (4 * PC);
    o[tid]          = grp;
    o[PC + tid]     = var;
    o[2 * PC + tid] = m3 / st3;
    o[3 * PC + tid] = m4 / (st3 * stdv);
}

// ---------------------------------------------------------------------------
// Fused kernel: streaming loop identical to the proven 6.45 TB/s pass1;
// everything after the loop lives behind a __noinline__ call.
// Shift y = x - 0.5 keeps all cancellation factors O(1) for uniform-ish data
// while remaining algebraically exact for any input.
// ---------------------------------------------------------------------------
__global__ __launch_bounds__(256)
void hom_fused(const float* __restrict__ x, const float* __restrict__ p_ptr,
               float* __restrict__ out)
{
    const int b     = blockIdx.y;
    const int chunk = blockIdx.x;
    const int tid   = threadIdx.x;
    const int c4    = tid & (C4 - 1);   // 0..63  channel group
    const int tl    = tid >> 6;         // 0..3   time lane

    const float p = p_ptr[0];
    const bool p_is_one = (p == 1.0f);

    const float4* __restrict__ x4 = reinterpret_cast<const float4*>(x);
    const int t0   = chunk * TCHUNK + tl;
    int idx        = (b * PT + t0) * C4 + c4;   // max ~16.8M, fits int
    const int step = TLANES * C4;

    float4 s1 = make_float4(0.f, 0.f, 0.f, 0.f);
    float4 s2 = s1, s3 = s1, s4 = s1, sp = s1;

    if (p_is_one) {
        #pragma unroll 4
        for (int i = 0; i < ITERS; ++i, idx += step) {
            float4 v = x4[idx];
            {
                float y = v.x - 0.5f, y2 = y * y;
                s1.x += y; s2.x += y2; s3.x += y2 * y; s4.x += y2 * y2;
            }
            {
                float y = v.y - 0.5f, y2 = y * y;
                s1.y += y; s2.y += y2; s3.y += y2 * y; s4.y += y2 * y2;
            }
            {
                float y = v.z - 0.5f, y2 = y * y;
                s1.z += y; s2.z += y2; s3.z += y2 * y; s4.z += y2 * y2;
            }
            {
                float y = v.w - 0.5f, y2 = y * y;
                s1.w += y; s2.w += y2; s3.w += y2 * y; s4.w += y2 * y2;
            }
        }
        // sp stays zero; the reducer derives grp = E[y] + 0.5 when p==1.
    } else {
        #pragma unroll 2
        for (int i = 0; i < ITERS; ++i, idx += step) {
            float4 v = x4[idx];
            {
                float y = v.x - 0.5f, y2 = y * y;
                s1.x += y; s2.x += y2; s3.x += y2 * y; s4.x += y2 * y2;
                sp.x += powf(v.x, p);
            }
            {
                float y = v.y - 0.5f, y2 = y * y;
                s1.y += y; s2.y += y2; s3.y += y2 * y; s4.y += y2 * y2;
                sp.y += powf(v.y, p);
            }
            {
                float y = v.z - 0.5f, y2 = y * y;
                s1.z += y; s2.z += y2; s3.z += y2 * y; s4.z += y2 * y2;
                sp.z += powf(v.z, p);
            }
            {
                float y = v.w - 0.5f, y2 = y * y;
                s1.w += y; s2.w += y2; s3.w += y2 * y; s4.w += y2 * y2;
                sp.w += powf(v.w, p);
            }
        }
    }

    hom_tail(s1, s2, s3, s4, sp, b, tid, c4, tl, p_is_one, p, out);
}

extern "C" void kernel_launch(void* const* d_in, const int* in_sizes, int n_in,
                              void* d_out, int out_size)
{
    const float* x = (const float*)d_in[0];
    const float* p = (const float*)d_in[1];
    float* out     = (float*)d_out;

    dim3 grid(NSPLIT, PB);
    hom_fused<<<grid, 256>>>(x, p, out);
}

// round 17
// speedup vs baseline: 1.3011x; 1.0060x over previous
#include <cuda_runtime.h>

// Problem constants (fixed by setup_inputs): x[B, T, C], pool over T.
#define PB 32
#define PT 8192
#define PC 256
#define NSPLIT 16                 // T-chunks per batch -> grid 512 (one wave)
#define TCHUNK (PT / NSPLIT)      // 512 timesteps per block
#define TLANES 4                  // time-lanes inside a block
#define ITERS (TCHUNK / TLANES)   // 128 float4 loads per thread
#define C4 (PC / 4)               // 64 float4 per row
#define NMOM 5                    // y, y^2, y^3, y^4, x^p

// Global accumulators: [B][NMOM][C] floats = 160 KB. Zero-initialized at load;
// the per-batch reducer block zeroes them again after reading, so every graph
// replay starts from zeros (deterministic up to fp32 atomic ordering noise).
__device__ float g_sums[PB * NMOM * PC];
// Per-batch arrival counters, same self-resetting discipline.
__device__ int g_count[PB];

// ---------------------------------------------------------------------------
// Tail: __noinline__, called AFTER the accumulators are parked in shared
// memory, so nothing but a pointer and three ints crosses the ABI boundary.
// The streaming loop's compiled region is then shaped exactly like the
// standalone 6.45 TB/s pass1 (loop + smem stores, accumulators dead at call).
// ---------------------------------------------------------------------------
__device__ __noinline__ void hom_tail(
    float4 (*sm)[NMOM][C4], int b, int tid, int p_is_one,
    float* __restrict__ out)
{
    __syncthreads();

    // Each thread owns one channel c = tid: collapse 4 lanes, 5 atomics.
    {
        const int g    = tid >> 2;   // float4 group
        const int comp = tid & 3;    // component
        #pragma unroll
        for (int m = 0; m < NMOM; ++m) {
            float v = 0.f;
            #pragma unroll
            for (int k = 0; k < TLANES; ++k) {
                float4 q = sm[k][m][g];
                v += (comp == 0) ? q.x : (comp == 1) ? q.y
                   : (comp == 2) ? q.z : q.w;
            }
            atomicAdd(&g_sums[(b * NMOM + m) * PC + tid], v);
        }
    }

    // ---- last-block-per-batch epilogue ----
    __threadfence();   // make this block's REDs visible before counter bump

    __shared__ int is_last;
    if (tid == 0)
        is_last = (atomicAdd(&g_count[b], 1) == NSPLIT - 1);
    __syncthreads();
    if (!is_last) return;

    if (tid == 0) g_count[b] = 0;   // reset for the next graph replay

    // Read the 5 accumulated moments for channel tid (L2, bypass L1), then
    // zero them for the next replay.
    float t[NMOM];
    #pragma unroll
    for (int m = 0; m < NMOM; ++m) {
        float* a = &g_sums[(b * NMOM + m) * PC + tid];
        t[m] = __ldcg(a);
        __stcg(a, 0.f);
    }

    const float invT = 1.0f / (float)PT;
    const float d  = t[0] * invT;   // E[y],  y = x - 0.5
    const float e2 = t[1] * invT;   // E[y^2]
    const float e3 = t[2] * invT;   // E[y^3]
    const float e4 = t[3] * invT;   // E[y^4]

    const float d2  = d * d;
    const float var = e2 - d2;
    const float m3  = e3 - 3.0f * d * e2 + 2.0f * d * d2;
    const float m4  = e4 - 4.0f * d * e3 + 6.0f * d2 * e2 - 3.0f * d2 * d2;

    const float grp = p_is_one ? (d + 0.5f) : (t[4] * invT);

    const float stdv = sqrtf(var + 1e-6f);
    const float st3  = stdv * stdv * stdv;

    float* o = out + b * (4 * PC);
    o[tid]          = grp;
    o[PC + tid]     = var;
    o[2 * PC + tid] = m3 / st3;
    o[3 * PC + tid] = m4 / (st3 * stdv);
}

// ---------------------------------------------------------------------------
// Fused kernel: streaming loop + smem parking identical in shape to the
// proven 6.45 TB/s standalone pass1; everything else behind a __noinline__
// call that carries no register state.
// Shift y = x - 0.5 keeps all cancellation factors O(1) for uniform-ish data
// while remaining algebraically exact for any input.
// ---------------------------------------------------------------------------
__global__ __launch_bounds__(256)
void hom_fused(const float* __restrict__ x, const float* __restrict__ p_ptr,
               float* __restrict__ out)
{
    const int b     = blockIdx.y;
    const int chunk = blockIdx.x;
    const int tid   = threadIdx.x;
    const int c4    = tid & (C4 - 1);   // 0..63  channel group
    const int tl    = tid >> 6;         // 0..3   time lane

    const float p = p_ptr[0];
    const bool p_is_one = (p == 1.0f);

    const float4* __restrict__ x4 = reinterpret_cast<const float4*>(x);
    const int t0   = chunk * TCHUNK + tl;
    int idx        = (b * PT + t0) * C4 + c4;   // max ~16.8M, fits int
    const int step = TLANES * C4;

    float4 s1 = make_float4(0.f, 0.f, 0.f, 0.f);
    float4 s2 = s1, s3 = s1, s4 = s1, sp = s1;

    if (p_is_one) {
        #pragma unroll 4
        for (int i = 0; i < ITERS; ++i, idx += step) {
            float4 v = x4[idx];
            {
                float y = v.x - 0.5f, y2 = y * y;
                s1.x += y; s2.x += y2; s3.x += y2 * y; s4.x += y2 * y2;
            }
            {
                float y = v.y - 0.5f, y2 = y * y;
                s1.y += y; s2.y += y2; s3.y += y2 * y; s4.y += y2 * y2;
            }
            {
                float y = v.z - 0.5f, y2 = y * y;
                s1.z += y; s2.z += y2; s3.z += y2 * y; s4.z += y2 * y2;
            }
            {
                float y = v.w - 0.5f, y2 = y * y;
                s1.w += y; s2.w += y2; s3.w += y2 * y; s4.w += y2 * y2;
            }
        }
        // sp stays zero; the reducer derives grp = E[y] + 0.5 when p==1.
    } else {
        #pragma unroll 2
        for (int i = 0; i < ITERS; ++i, idx += step) {
            float4 v = x4[idx];
            {
                float y = v.x - 0.5f, y2 = y * y;
                s1.x += y; s2.x += y2; s3.x += y2 * y; s4.x += y2 * y2;
                sp.x += powf(v.x, p);
            }
            {
                float y = v.y - 0.5f, y2 = y * y;
                s1.y += y; s2.y += y2; s3.y += y2 * y; s4.y += y2 * y2;
                sp.y += powf(v.y, p);
            }
            {
                float y = v.z - 0.5f, y2 = y * y;
                s1.z += y; s2.z += y2; s3.z += y2 * y; s4.z += y2 * y2;
                sp.z += powf(v.z, p);
            }
            {
                float y = v.w - 0.5f, y2 = y * y;
                s1.w += y; s2.w += y2; s3.w += y2 * y; s4.w += y2 * y2;
                sp.w += powf(v.w, p);
            }
        }
    }

    // Park accumulators in shared memory (same stores as standalone pass1);
    // accumulators are dead past this point, so no state crosses the call.
    __shared__ float4 sm[TLANES][NMOM][C4];   // 20 KB
    sm[tl][0][c4] = s1;
    sm[tl][1][c4] = s2;
    sm[tl][2][c4] = s3;
    sm[tl][3][c4] = s4;
    sm[tl][4][c4] = sp;

    hom_tail(sm, b, tid, (int)p_is_one, out);
}

extern "C" void kernel_launch(void* const* d_in, const int* in_sizes, int n_in,
                              void* d_out, int out_size)
{
    const float* x = (const float*)d_in[0];
    const float* p = (const float*)d_in[1];
    float* out     = (float*)d_out;

    dim3 grid(NSPLIT, PB);
    hom_fused<<<grid, 256>>>(x, p, out);
}